// round 7
// baseline (speedup 1.0000x reference)
#include <cuda_runtime.h>
#include <cuda_bf16.h>
#include <cstdint>

#define CIN   256
#define EDIM  16
#define LWIN  64
#define MDIM  64
#define HDIM  64
#define COUT  256
#define BATCH 16
#define NSTEP 2048

// ---------------- scratch ----------------
__device__ float g_TW[CIN * LWIN * HDIM];
__device__ float g_Tb[CIN * LWIN * HDIM];
__device__ float g_preW[NSTEP * BATCH * HDIM];
__device__ float g_preb[NSTEP * BATCH * HDIM];
__device__ float g_m[NSTEP * BATCH * MDIM];

__device__ __forceinline__ float sigmoidf_fast(float x) {
    return 1.0f / (1.0f + __expf(-x));
}
__device__ __forceinline__ unsigned long long packf2(float lo, float hi) {
    unsigned long long r;
    asm("mov.b64 %0, {%1, %2};" : "=l"(r) : "f"(lo), "f"(hi));
    return r;
}
__device__ __forceinline__ unsigned long long fma2(unsigned long long a,
                                                   unsigned long long b,
                                                   unsigned long long c) {
    unsigned long long d;
    asm("fma.rn.f32x2 %0, %1, %2, %3;" : "=l"(d) : "l"(a), "l"(b), "l"(c));
    return d;
}
__device__ __forceinline__ unsigned long long add2(unsigned long long a,
                                                   unsigned long long b) {
    unsigned long long d;
    asm("add.rn.f32x2 %0, %1, %2;" : "=l"(d) : "l"(a), "l"(b));
    return d;
}
__device__ __forceinline__ float hsum2(unsigned long long v) {
    float lo, hi;
    asm("mov.b64 {%0, %1}, %2;" : "=f"(lo), "=f"(hi) : "l"(v));
    return lo + hi;
}

// ---------------- kernel 1: token/position contribution tables ----------------
__global__ void table_kernel(const float* __restrict__ emb,
                             const float* __restrict__ Wew,
                             const float* __restrict__ bew) {
    int c = blockIdx.x >> 6;
    int l = blockIdx.x & 63;
    int h = threadIdx.x;
    float aw = 0.f, ab = 0.f;
#pragma unroll
    for (int e = 0; e < EDIM; ++e) {
        float ev = emb[c * EDIM + e];
        int row = MDIM + l * EDIM + e;
        aw += ev * Wew[row * HDIM + h];
        ab += ev * bew[row * HDIM + h];
    }
    g_TW[(c * LWIN + l) * HDIM + h] = aw;
    g_Tb[(c * LWIN + l) * HDIM + h] = ab;
}

// ---------------- kernel 2: window pre-activations ----------------
__global__ void pre_kernel(const int* __restrict__ x0) {
    int tb = blockIdx.x;
    int t = tb >> 4, b = tb & 15;
    int h = threadIdx.x;
    float aw = 0.f, ab = 0.f;
#pragma unroll 4
    for (int l = 0; l < LWIN; ++l) {
        int k = t + l;
        int tok = (k < LWIN) ? 0 : x0[b * NSTEP + (k - LWIN)];
        aw += g_TW[(tok * LWIN + l) * HDIM + h];
        ab += g_Tb[(tok * LWIN + l) * HDIM + h];
    }
    g_preW[(t * BATCH + b) * HDIM + h] = aw;
    g_preb[(t * BATCH + b) * HDIM + h] = ab;
}

// ---------------- kernel 3: sequential scan ----------------
// 16 clusters (batch) x 8 CTAs (i-slices of 8), 512 threads/CTA.
// Cross-CTA sync via mbarrier producer/consumer (no barrier.cluster per step).
__global__ void __launch_bounds__(512, 1)
scan_kernel(const float* __restrict__ Wew, const float* __restrict__ Web,
            const float* __restrict__ Wdw, const float* __restrict__ Wdb,
            const float* __restrict__ bew, const float* __restrict__ beb,
            const float* __restrict__ bdw, const float* __restrict__ bdb) {
    __shared__ __align__(16) float sM[2][MDIM];   // ping-pong m
    __shared__ __align__(16) float sH[2][HDIM];   // hW, hb
    __shared__ float sP[4 * 128];
    __shared__ float sRed[16];
    __shared__ float sBm[8];
    __shared__ float sBdp[8 * 65];
    __shared__ __align__(8) unsigned long long mbar[2];

    const int tid = threadIdx.x;
    const int b = blockIdx.x >> 3;
    const int r = blockIdx.x & 7;

    const int il = tid >> 6, j = tid & 63;
    const int ig = r * 8 + il;

    // bilinear weight slice packed as f32x2 over h: wdp[k] = (Wdw[2k][col], Wdw[2k+1][col])
    unsigned long long wdp[32];
    const int col = ig * 64 + j;
#pragma unroll
    for (int k = 0; k < 32; ++k)
        wdp[k] = packf2(Wdw[(2 * k) * 4096 + col], Wdw[(2 * k + 1) * 4096 + col]);
    const float wdecb = Wdb[col];

    // enc fragment packed: thread (q, path, h6) covers m rows q*16..q*16+15
    const int q = tid >> 7;
    const int rest = tid & 127;
    const int path = rest >> 6;
    const int h6 = rest & 63;
    const float* Aarr = path ? bew : Wew;
    unsigned long long aencp[8];
#pragma unroll
    for (int k = 0; k < 8; ++k)
        aencp[k] = packf2(Aarr[(q * 16 + 2 * k) * 64 + h6],
                          Aarr[(q * 16 + 2 * k + 1) * 64 + h6]);

    float encb = 0.f;
    const float* pp = nullptr;
    float pre_next = 0.f;
    if (tid < 128) {
        encb = path ? beb[h6] : Web[h6];
        pp = (path ? g_preb : g_preW) + b * 64 + h6;
        pre_next = pp[0];
    }
    float bdb_r = 0.f;
    if (tid < 64) bdb_r = bdb[r * 8 + (tid >> 3)];
    {
        int bil = tid >> 6, hh = tid & 63;
        sBdp[bil * 65 + hh] = bdw[hh * 64 + r * 8 + bil];
    }
    if (tid < 64) sM[0][tid] = 0.f;

    // shared-state-space addresses
    const uint32_t sM_sa = (uint32_t)__cvta_generic_to_shared(&sM[0][0]);
    const uint32_t sH_sa = (uint32_t)__cvta_generic_to_shared(&sH[0][0]);
    const uint32_t mb_sa = (uint32_t)__cvta_generic_to_shared(&mbar[0]);

    if (tid == 0) {
        asm volatile("mbarrier.init.shared.b64 [%0], %1;" :: "r"(mb_sa), "r"(64));
        asm volatile("mbarrier.init.shared.b64 [%0], %1;" :: "r"(mb_sa + 8), "r"(64));
        asm volatile("fence.mbarrier_init.release.cluster;" ::: "memory");
    }
    __syncthreads();
    asm volatile("barrier.cluster.arrive.aligned;\n" ::: "memory");
    asm volatile("barrier.cluster.wait.aligned;\n" ::: "memory");

#pragma unroll 1
    for (int t = 0; t < NSTEP; ++t) {
        const uint32_t mcur_sa = sM_sa + (t & 1) * (MDIM * 4);

        // ---- consumer wait: m buffer for this step is complete
        if (t > 0) {
            uint32_t par = ((t - 1) >> 1) & 1;
            uint32_t bar = mb_sa + (t & 1) * 8;
            asm volatile(
                "{\n\t.reg .pred P;\n"
                "LW_%=: mbarrier.try_wait.parity.acquire.cluster.shared::cta.b64 P, [%0], %1, 0x989680;\n"
                "@P bra LD_%=;\n"
                "bra LW_%=;\n"
                "LD_%=:\n\t}"
                :: "r"(bar), "r"(par) : "memory");
        }
        float pre_cur = pre_next;

        // ---- stage 1: enc partials (packed f32x2)
        {
            unsigned long long a0 = 0ull, a1 = 0ull;
            uint32_t ma = mcur_sa + q * 64;
#pragma unroll
            for (int k = 0; k < 4; ++k) {
                unsigned long long m0, m1;
                asm volatile("ld.shared.v2.u64 {%0, %1}, [%2];"
                             : "=l"(m0), "=l"(m1) : "r"(ma + k * 16));
                a0 = fma2(m0, aencp[2 * k], a0);
                a1 = fma2(m1, aencp[2 * k + 1], a1);
            }
            sP[q * 128 + rest] = hsum2(add2(a0, a1));
        }
        __syncthreads();

        // ---- stage 2: finalize z, sigmoid, publish hW/hb; prefetch next pre
        if (tid < 128) {
            float z = sP[rest] + sP[128 + rest] + sP[256 + rest] + sP[384 + rest]
                    + pre_cur + encb;
            sH[path][h6] = sigmoidf_fast(z);
            if (t + 1 < NSTEP) pre_next = pp[(t + 1) * (BATCH * 64)];
        }
        __syncthreads();

        // ---- stage 3a (warps 0-1): bm
        if (tid < 64) {
            int bil = tid >> 3, s8 = tid & 7;
            float p = 0.f;
#pragma unroll
            for (int kk = 0; kk < 8; ++kk) {
                int hh = s8 * 8 + kk;
                p += sH[1][hh] * sBdp[bil * 65 + hh];
            }
            p += __shfl_xor_sync(0xffffffffu, p, 1);
            p += __shfl_xor_sync(0xffffffffu, p, 2);
            p += __shfl_xor_sync(0xffffffffu, p, 4);
            if (s8 == 0) sBm[bil] = p + bdb_r;
        }

        // ---- stage 3b: bilinear, packed f32x2
        {
            float mj;
            asm volatile("ld.shared.f32 %0, [%1];" : "=f"(mj) : "r"(mcur_sa + j * 4));
            unsigned long long a0 = 0ull, a1 = 0ull;
#pragma unroll
            for (int k = 0; k < 16; ++k) {
                unsigned long long h0, h1;
                asm volatile("ld.shared.v2.u64 {%0, %1}, [%2];"
                             : "=l"(h0), "=l"(h1) : "r"(sH_sa + k * 16));
                a0 = fma2(h0, wdp[2 * k], a0);
                a1 = fma2(h1, wdp[2 * k + 1], a1);
            }
            float acc2 = hsum2(add2(a0, a1));
            float val = (acc2 + wdecb) * mj;
#pragma unroll
            for (int off = 16; off; off >>= 1)
                val += __shfl_xor_sync(0xffffffffu, val, off);
            if ((tid & 31) == 0) sRed[tid >> 5] = val;
        }
        __syncthreads();

        // ---- stage 4: finalize m[i], broadcast to peers, signal barriers
        if (tid < 8) {
            float tot = sRed[tid * 2] + sRed[tid * 2 + 1] + sBm[tid];
            float nm = sigmoidf_fast(tot);
            int nxt = (t + 1) & 1;
            int igo = r * 8 + tid;
            sM[nxt][igo] = nm;                          // local copy
            g_m[(t * BATCH + b) * MDIM + igo] = nm;     // persist for loss
            if (t + 1 < NSTEP) {
                uint32_t a = sM_sa + nxt * (MDIM * 4) + igo * 4;
                uint32_t barn = mb_sa + nxt * 8;
#pragma unroll
                for (int p2 = 0; p2 < 8; ++p2) {
                    if (p2 == r) continue;
                    uint32_t ra;
                    asm volatile("mapa.shared::cluster.u32 %0, %1, %2;"
                                 : "=r"(ra) : "r"(a), "r"(p2));
                    asm volatile("st.shared::cluster.f32 [%0], %1;"
                                 :: "r"(ra), "f"(nm) : "memory");
                }
                // local arrive (orders local store)
                asm volatile("mbarrier.arrive.release.cluster.shared::cta.b64 _, [%0];"
                             :: "r"(barn) : "memory");
#pragma unroll
                for (int p2 = 0; p2 < 8; ++p2) {
                    if (p2 == r) continue;
                    uint32_t rb;
                    asm volatile("mapa.shared::cluster.u32 %0, %1, %2;"
                                 : "=r"(rb) : "r"(barn), "r"(p2));
                    asm volatile("mbarrier.arrive.release.cluster.shared::cluster.b64 _, [%0];"
                                 :: "r"(rb) : "memory");
                }
            }
        }
        // no trailing CTA-wide barrier: next-step consumer wait provides ordering
    }

    asm volatile("barrier.cluster.arrive.aligned;\n" ::: "memory");
    asm volatile("barrier.cluster.wait.aligned;\n" ::: "memory");
}

// ---------------- kernel 4: loss epilogue ----------------
#define LOSS_R 16
__global__ void __launch_bounds__(256, 2)
loss_kernel(const int* __restrict__ x0, const float* __restrict__ decw,
            const float* __restrict__ decb, float* __restrict__ out) {
    __shared__ float sm[LOSS_R][64];
    __shared__ float sredm[8];
    __shared__ float sreds[8];
    __shared__ float syl[LOSS_R];
    const int c = threadIdx.x;
    const int row0 = blockIdx.x * LOSS_R;

    float w[64];
#pragma unroll
    for (int i = 0; i < 64; ++i)
        w[i] = decw[i * COUT + c];
    const float db = decb[c];

    for (int idx = c; idx < LOSS_R * 64; idx += 256)
        sm[idx >> 6][idx & 63] = g_m[row0 * 64 + idx];
    __syncthreads();

#pragma unroll 1
    for (int rr = 0; rr < LOSS_R; ++rr) {
        int row = row0 + rr;
        int t = row >> 4, bb = row & 15;
        float logit = db;
#pragma unroll
        for (int i = 0; i < 64; ++i)
            logit += sm[rr][i] * w[i];
        int y = x0[bb * NSTEP + t];
        if (c == y) syl[rr] = logit;

        float mx = logit;
#pragma unroll
        for (int off = 16; off; off >>= 1)
            mx = fmaxf(mx, __shfl_xor_sync(0xffffffffu, mx, off));
        if ((c & 31) == 0) sredm[c >> 5] = mx;
        __syncthreads();
        mx = sredm[0];
#pragma unroll
        for (int ww = 1; ww < 8; ++ww) mx = fmaxf(mx, sredm[ww]);

        float ex = __expf(logit - mx);
#pragma unroll
        for (int off = 16; off; off >>= 1)
            ex += __shfl_xor_sync(0xffffffffu, ex, off);
        if ((c & 31) == 0) sreds[c >> 5] = ex;
        __syncthreads();
        if (c == 0) {
            float S = 0.f;
#pragma unroll
            for (int ww = 0; ww < 8; ++ww) S += sreds[ww];
            float lse = mx + __logf(S);
            out[row] = (lse - syl[rr]) * 1.4426950408889634f;
        }
    }
}

// ---------------- launch ----------------
extern "C" void kernel_launch(void* const* d_in, const int* in_sizes, int n_in,
                              void* d_out, int out_size) {
    const int*   x0   = (const int*)d_in[0];
    const float* emb  = (const float*)d_in[1];
    const float* Wew  = (const float*)d_in[2];
    const float* Web  = (const float*)d_in[3];
    const float* Wdw  = (const float*)d_in[4];
    const float* Wdb  = (const float*)d_in[5];
    const float* bew  = (const float*)d_in[6];
    const float* beb  = (const float*)d_in[7];
    const float* bdw  = (const float*)d_in[8];
    const float* bdb  = (const float*)d_in[9];
    const float* decw = (const float*)d_in[10];
    const float* decb = (const float*)d_in[11];
    float* out = (float*)d_out;

    table_kernel<<<CIN * LWIN, 64>>>(emb, Wew, bew);
    pre_kernel<<<NSTEP * BATCH, 64>>>(x0);

    cudaLaunchConfig_t cfg = {};
    cfg.gridDim = dim3(128, 1, 1);
    cfg.blockDim = dim3(512, 1, 1);
    cfg.dynamicSmemBytes = 0;
    cfg.stream = 0;
    cudaLaunchAttribute attr[1];
    attr[0].id = cudaLaunchAttributeClusterDimension;
    attr[0].val.clusterDim.x = 8;
    attr[0].val.clusterDim.y = 1;
    attr[0].val.clusterDim.z = 1;
    cfg.attrs = attr;
    cfg.numAttrs = 1;
    cudaLaunchKernelEx(&cfg, scan_kernel, Wew, Web, Wdw, Wdb, bew, beb, bdw, bdb);

    loss_kernel<<<(NSTEP * BATCH) / LOSS_R, 256>>>(x0, decw, decb, out);
}

// round 8
// speedup vs baseline: 1.4687x; 1.4687x over previous
#include <cuda_runtime.h>
#include <cuda_bf16.h>
#include <cstdint>

#define CIN   256
#define EDIM  16
#define LWIN  64
#define MDIM  64
#define HDIM  64
#define COUT  256
#define BATCH 16
#define NSTEP 2048

// ---------------- scratch ----------------
__device__ float g_TW[CIN * LWIN * HDIM];
__device__ float g_Tb[CIN * LWIN * HDIM];
__device__ float g_preW[NSTEP * BATCH * HDIM];
__device__ float g_preb[NSTEP * BATCH * HDIM];
__device__ float g_m[NSTEP * BATCH * MDIM];

__device__ __forceinline__ float sigmoidf_fast(float x) {
    return 1.0f / (1.0f + __expf(-x));
}
__device__ __forceinline__ unsigned long long packf2(float lo, float hi) {
    unsigned long long r;
    asm("mov.b64 %0, {%1, %2};" : "=l"(r) : "f"(lo), "f"(hi));
    return r;
}
__device__ __forceinline__ unsigned long long fma2(unsigned long long a,
                                                   unsigned long long b,
                                                   unsigned long long c) {
    unsigned long long d;
    asm("fma.rn.f32x2 %0, %1, %2, %3;" : "=l"(d) : "l"(a), "l"(b), "l"(c));
    return d;
}
__device__ __forceinline__ unsigned long long add2(unsigned long long a,
                                                   unsigned long long b) {
    unsigned long long d;
    asm("add.rn.f32x2 %0, %1, %2;" : "=l"(d) : "l"(a), "l"(b));
    return d;
}
__device__ __forceinline__ float hsum2(unsigned long long v) {
    float lo, hi;
    asm("mov.b64 {%0, %1}, %2;" : "=f"(lo), "=f"(hi) : "l"(v));
    return lo + hi;
}

// ---------------- kernel 1: token/position contribution tables ----------------
__global__ void table_kernel(const float* __restrict__ emb,
                             const float* __restrict__ Wew,
                             const float* __restrict__ bew) {
    int c = blockIdx.x >> 6;
    int l = blockIdx.x & 63;
    int h = threadIdx.x;
    float aw = 0.f, ab = 0.f;
#pragma unroll
    for (int e = 0; e < EDIM; ++e) {
        float ev = emb[c * EDIM + e];
        int row = MDIM + l * EDIM + e;
        aw += ev * Wew[row * HDIM + h];
        ab += ev * bew[row * HDIM + h];
    }
    g_TW[(c * LWIN + l) * HDIM + h] = aw;
    g_Tb[(c * LWIN + l) * HDIM + h] = ab;
}

// ---------------- kernel 2: window pre-activations ----------------
__global__ void pre_kernel(const int* __restrict__ x0) {
    int tb = blockIdx.x;
    int t = tb >> 4, b = tb & 15;
    int h = threadIdx.x;
    float aw = 0.f, ab = 0.f;
#pragma unroll 4
    for (int l = 0; l < LWIN; ++l) {
        int k = t + l;
        int tok = (k < LWIN) ? 0 : x0[b * NSTEP + (k - LWIN)];
        aw += g_TW[(tok * LWIN + l) * HDIM + h];
        ab += g_Tb[(tok * LWIN + l) * HDIM + h];
    }
    g_preW[(t * BATCH + b) * HDIM + h] = aw;
    g_preb[(t * BATCH + b) * HDIM + h] = ab;
}

// ---------------- kernel 3: sequential scan ----------------
// 16 clusters (batch) x 8 CTAs (i-slices of 8), 512 threads/CTA.
// Per-step cross-CTA sync: count-8 mbarriers, one arrive per source CTA,
// single-thread consumer wait + __syncthreads release.
__global__ void __launch_bounds__(512, 1)
scan_kernel(const float* __restrict__ Wew, const float* __restrict__ Web,
            const float* __restrict__ Wdw, const float* __restrict__ Wdb,
            const float* __restrict__ bew, const float* __restrict__ beb,
            const float* __restrict__ bdw, const float* __restrict__ bdb) {
    __shared__ __align__(16) float sM[2][MDIM];   // ping-pong m
    __shared__ __align__(16) float sH[2][HDIM];   // hW, hb
    __shared__ float sP[4 * 128];
    __shared__ float sRed[16];
    __shared__ float sBm[8];
    __shared__ float sBdp[8 * 65];
    __shared__ __align__(8) unsigned long long mbar[2];

    const int tid = threadIdx.x;
    const int b = blockIdx.x >> 3;
    const int r = blockIdx.x & 7;

    const int il = tid >> 6, j = tid & 63;
    const int ig = r * 8 + il;

    // bilinear weight slice packed f32x2 over h
    unsigned long long wdp[32];
    const int col = ig * 64 + j;
#pragma unroll
    for (int k = 0; k < 32; ++k)
        wdp[k] = packf2(Wdw[(2 * k) * 4096 + col], Wdw[(2 * k + 1) * 4096 + col]);
    const float wdecb = Wdb[col];

    // enc fragment: thread (q, path, h6) covers m rows q*16..q*16+15
    const int q = tid >> 7;
    const int rest = tid & 127;
    const int path = rest >> 6;
    const int h6 = rest & 63;
    const float* Aarr = path ? bew : Wew;
    unsigned long long aencp[8];
#pragma unroll
    for (int k = 0; k < 8; ++k)
        aencp[k] = packf2(Aarr[(q * 16 + 2 * k) * 64 + h6],
                          Aarr[(q * 16 + 2 * k + 1) * 64 + h6]);

    float encb = 0.f;
    const float* pp = nullptr;
    float pre_next = 0.f;
    if (tid < 128) {
        encb = path ? beb[h6] : Web[h6];
        pp = (path ? g_preb : g_preW) + b * 64 + h6;
        pre_next = pp[0];
    }
    float bdb_r = 0.f;
    if (tid < 64) bdb_r = bdb[r * 8 + (tid >> 3)];
    {
        int bil = tid >> 6, hh = tid & 63;
        sBdp[bil * 65 + hh] = bdw[hh * 64 + r * 8 + bil];
    }
    if (tid < 64) sM[0][tid] = 0.f;

    const uint32_t sM_sa = (uint32_t)__cvta_generic_to_shared(&sM[0][0]);
    const uint32_t sH_sa = (uint32_t)__cvta_generic_to_shared(&sH[0][0]);
    const uint32_t mb_sa = (uint32_t)__cvta_generic_to_shared(&mbar[0]);

    if (tid == 0) {
        asm volatile("mbarrier.init.shared.b64 [%0], %1;" :: "r"(mb_sa), "r"(8));
        asm volatile("mbarrier.init.shared.b64 [%0], %1;" :: "r"(mb_sa + 8), "r"(8));
        asm volatile("fence.mbarrier_init.release.cluster;" ::: "memory");
    }
    __syncthreads();
    asm volatile("barrier.cluster.arrive.aligned;\n" ::: "memory");
    asm volatile("barrier.cluster.wait.aligned;\n" ::: "memory");

#pragma unroll 1
    for (int t = 0; t < NSTEP; ++t) {
        const uint32_t mcur_sa = sM_sa + (t & 1) * (MDIM * 4);

        // ---- consumer: ONE thread waits for this step's m buffer, CTA syncs
        if (t > 0) {
            if (tid == 0) {
                uint32_t par = ((t - 1) >> 1) & 1;
                uint32_t bar = mb_sa + (t & 1) * 8;
                asm volatile(
                    "{\n\t.reg .pred P;\n"
                    "LW_%=: mbarrier.try_wait.parity.acquire.cluster.shared::cta.b64 P, [%0], %1, 0x989680;\n"
                    "@P bra LD_%=;\n"
                    "bra LW_%=;\n"
                    "LD_%=:\n\t}"
                    :: "r"(bar), "r"(par) : "memory");
            }
            __syncthreads();
        }
        float pre_cur = pre_next;

        // ---- stage 1: enc partials (4-way split, packed f32x2)
        {
            unsigned long long a0 = 0ull, a1 = 0ull;
            uint32_t ma = mcur_sa + q * 64;
#pragma unroll
            for (int k = 0; k < 4; ++k) {
                unsigned long long m0, m1;
                asm volatile("ld.shared.v2.u64 {%0, %1}, [%2];"
                             : "=l"(m0), "=l"(m1) : "r"(ma + k * 16));
                a0 = fma2(m0, aencp[2 * k], a0);
                a1 = fma2(m1, aencp[2 * k + 1], a1);
            }
            sP[q * 128 + rest] = hsum2(add2(a0, a1));
        }
        __syncthreads();

        // ---- stage 2: finalize z, sigmoid, publish hW/hb; prefetch next pre
        if (tid < 128) {
            float z = sP[rest] + sP[128 + rest] + sP[256 + rest] + sP[384 + rest]
                    + pre_cur + encb;
            sH[path][h6] = sigmoidf_fast(z);
            if (t + 1 < NSTEP) pre_next = pp[(t + 1) * (BATCH * 64)];
        }
        __syncthreads();

        // ---- stage 3a (warps 0-1): bm
        if (tid < 64) {
            int bil = tid >> 3, s8 = tid & 7;
            float p = 0.f;
#pragma unroll
            for (int kk = 0; kk < 8; ++kk) {
                int hh = s8 * 8 + kk;
                p += sH[1][hh] * sBdp[bil * 65 + hh];
            }
            p += __shfl_xor_sync(0xffffffffu, p, 1);
            p += __shfl_xor_sync(0xffffffffu, p, 2);
            p += __shfl_xor_sync(0xffffffffu, p, 4);
            if (s8 == 0) sBm[bil] = p + bdb_r;
        }

        // ---- stage 3b: bilinear, packed f32x2
        {
            float mj;
            asm volatile("ld.shared.f32 %0, [%1];" : "=f"(mj) : "r"(mcur_sa + j * 4));
            unsigned long long a0 = 0ull, a1 = 0ull;
#pragma unroll
            for (int k = 0; k < 16; ++k) {
                unsigned long long h0, h1;
                asm volatile("ld.shared.v2.u64 {%0, %1}, [%2];"
                             : "=l"(h0), "=l"(h1) : "r"(sH_sa + k * 16));
                a0 = fma2(h0, wdp[2 * k], a0);
                a1 = fma2(h1, wdp[2 * k + 1], a1);
            }
            float acc2 = hsum2(add2(a0, a1));
            float val = (acc2 + wdecb) * mj;
#pragma unroll
            for (int off = 16; off; off >>= 1)
                val += __shfl_xor_sync(0xffffffffu, val, off);
            if ((tid & 31) == 0) sRed[tid >> 5] = val;
        }
        __syncthreads();

        // ---- stage 4: finalize m, lane p ships full chunk to CTA p, one arrive
        if (tid < 8) {
            float tot = sRed[tid * 2] + sRed[tid * 2 + 1] + sBm[tid];
            float nm = sigmoidf_fast(tot);
            int igo = r * 8 + tid;
            g_m[(t * BATCH + b) * MDIM + igo] = nm;     // persist for loss
            if (t + 1 < NSTEP) {
                // butterfly-gather this CTA's 8-float chunk into every lane
                float f[8];
#pragma unroll
                for (int k = 0; k < 8; ++k)
                    f[k] = __shfl_sync(0x000000ffu, nm, k);
                unsigned long long d0 = packf2(f[0], f[1]);
                unsigned long long d1 = packf2(f[2], f[3]);
                unsigned long long d2 = packf2(f[4], f[5]);
                unsigned long long d3 = packf2(f[6], f[7]);

                int nxt = (t + 1) & 1;
                uint32_t dst = sM_sa + nxt * (MDIM * 4) + r * 32;  // chunk slot r
                uint32_t barn = mb_sa + nxt * 8;
                int p2 = tid;                                      // destination CTA
                if (p2 == r) {
                    asm volatile("st.shared.u64 [%0], %1;"      :: "r"(dst),      "l"(d0) : "memory");
                    asm volatile("st.shared.u64 [%0], %1;"      :: "r"(dst + 8),  "l"(d1) : "memory");
                    asm volatile("st.shared.u64 [%0], %1;"      :: "r"(dst + 16), "l"(d2) : "memory");
                    asm volatile("st.shared.u64 [%0], %1;"      :: "r"(dst + 24), "l"(d3) : "memory");
                    asm volatile("mbarrier.arrive.release.cluster.shared::cta.b64 _, [%0];"
                                 :: "r"(barn) : "memory");
                } else {
                    uint32_t ra, rb;
                    asm volatile("mapa.shared::cluster.u32 %0, %1, %2;"
                                 : "=r"(ra) : "r"(dst), "r"(p2));
                    asm volatile("mapa.shared::cluster.u32 %0, %1, %2;"
                                 : "=r"(rb) : "r"(barn), "r"(p2));
                    asm volatile("st.shared::cluster.u64 [%0], %1;" :: "r"(ra),      "l"(d0) : "memory");
                    asm volatile("st.shared::cluster.u64 [%0], %1;" :: "r"(ra + 8),  "l"(d1) : "memory");
                    asm volatile("st.shared::cluster.u64 [%0], %1;" :: "r"(ra + 16), "l"(d2) : "memory");
                    asm volatile("st.shared::cluster.u64 [%0], %1;" :: "r"(ra + 24), "l"(d3) : "memory");
                    asm volatile("mbarrier.arrive.release.cluster.shared::cluster.b64 _, [%0];"
                                 :: "r"(rb) : "memory");
                }
            }
        }
        // next step's single-thread wait + syncthreads provides CTA-wide release
    }

    asm volatile("barrier.cluster.arrive.aligned;\n" ::: "memory");
    asm volatile("barrier.cluster.wait.aligned;\n" ::: "memory");
}

// ---------------- kernel 4: loss epilogue ----------------
__global__ void __launch_bounds__(256)
loss_kernel(const int* __restrict__ x0, const float* __restrict__ decw,
            const float* __restrict__ decb, float* __restrict__ out) {
    __shared__ float sm[64];
    __shared__ float sred[8];
    __shared__ float syl;
    int row = blockIdx.x;
    int t = row >> 4, b = row & 15;
    int c = threadIdx.x;
    if (c < 64) sm[c] = g_m[row * 64 + c];
    __syncthreads();

    float logit = decb[c];
#pragma unroll
    for (int i = 0; i < 64; ++i)
        logit += sm[i] * decw[i * COUT + c];

    int y = x0[b * NSTEP + t];
    if (c == y) syl = logit;

    float mx = logit;
#pragma unroll
    for (int off = 16; off; off >>= 1)
        mx = fmaxf(mx, __shfl_xor_sync(0xffffffffu, mx, off));
    if ((c & 31) == 0) sred[c >> 5] = mx;
    __syncthreads();
    mx = sred[0];
#pragma unroll
    for (int w = 1; w < 8; ++w) mx = fmaxf(mx, sred[w]);

    float ex = __expf(logit - mx);
#pragma unroll
    for (int off = 16; off; off >>= 1)
        ex += __shfl_xor_sync(0xffffffffu, ex, off);
    __syncthreads();
    if ((c & 31) == 0) sred[c >> 5] = ex;
    __syncthreads();
    if (c == 0) {
        float S = 0.f;
#pragma unroll
        for (int w = 0; w < 8; ++w) S += sred[w];
        float lse = mx + __logf(S);
        out[row] = (lse - syl) * 1.4426950408889634f;
    }
}

// ---------------- launch ----------------
extern "C" void kernel_launch(void* const* d_in, const int* in_sizes, int n_in,
                              void* d_out, int out_size) {
    const int*   x0   = (const int*)d_in[0];
    const float* emb  = (const float*)d_in[1];
    const float* Wew  = (const float*)d_in[2];
    const float* Web  = (const float*)d_in[3];
    const float* Wdw  = (const float*)d_in[4];
    const float* Wdb  = (const float*)d_in[5];
    const float* bew  = (const float*)d_in[6];
    const float* beb  = (const float*)d_in[7];
    const float* bdw  = (const float*)d_in[8];
    const float* bdb  = (const float*)d_in[9];
    const float* decw = (const float*)d_in[10];
    const float* decb = (const float*)d_in[11];
    float* out = (float*)d_out;

    table_kernel<<<CIN * LWIN, 64>>>(emb, Wew, bew);
    pre_kernel<<<NSTEP * BATCH, 64>>>(x0);

    cudaLaunchConfig_t cfg = {};
    cfg.gridDim = dim3(128, 1, 1);
    cfg.blockDim = dim3(512, 1, 1);
    cfg.dynamicSmemBytes = 0;
    cfg.stream = 0;
    cudaLaunchAttribute attr[1];
    attr[0].id = cudaLaunchAttributeClusterDimension;
    attr[0].val.clusterDim.x = 8;
    attr[0].val.clusterDim.y = 1;
    attr[0].val.clusterDim.z = 1;
    cfg.attrs = attr;
    cfg.numAttrs = 1;
    cudaLaunchKernelEx(&cfg, scan_kernel, Wew, Web, Wdw, Wdb, bew, beb, bdw, bdb);

    loss_kernel<<<NSTEP * BATCH, 256>>>(x0, decw, decb, out);
}

// round 13
// speedup vs baseline: 1.8136x; 1.2349x over previous
#include <cuda_runtime.h>
#include <cuda_bf16.h>
#include <cstdint>

#define CIN   256
#define EDIM  16
#define LWIN  64
#define MDIM  64
#define HDIM  64
#define COUT  256
#define BATCH 16
#define NSTEP 2048

// ---------------- scratch ----------------
__device__ float g_TW[CIN * LWIN * HDIM];
__device__ float g_Tb[CIN * LWIN * HDIM];
__device__ float g_preW[NSTEP * BATCH * HDIM];
__device__ float g_preb[NSTEP * BATCH * HDIM];
__device__ float g_m[NSTEP * BATCH * MDIM];

__device__ __forceinline__ float sigmoidf_fast(float x) {
    return 1.0f / (1.0f + __expf(-x));
}
__device__ __forceinline__ unsigned long long packf2(float lo, float hi) {
    unsigned long long r;
    asm("mov.b64 %0, {%1, %2};" : "=l"(r) : "f"(lo), "f"(hi));
    return r;
}
__device__ __forceinline__ unsigned long long fma2(unsigned long long a,
                                                   unsigned long long b,
                                                   unsigned long long c) {
    unsigned long long d;
    asm("fma.rn.f32x2 %0, %1, %2, %3;" : "=l"(d) : "l"(a), "l"(b), "l"(c));
    return d;
}
__device__ __forceinline__ unsigned long long add2(unsigned long long a,
                                                   unsigned long long b) {
    unsigned long long d;
    asm("add.rn.f32x2 %0, %1, %2;" : "=l"(d) : "l"(a), "l"(b));
    return d;
}
__device__ __forceinline__ float hsum2(unsigned long long v) {
    float lo, hi;
    asm("mov.b64 {%0, %1}, %2;" : "=f"(lo), "=f"(hi) : "l"(v));
    return lo + hi;
}

// ---------------- kernel 1: token/position contribution tables ----------------
__global__ void table_kernel(const float* __restrict__ emb,
                             const float* __restrict__ Wew,
                             const float* __restrict__ bew) {
    int c = blockIdx.x >> 6;
    int l = blockIdx.x & 63;
    int h = threadIdx.x;
    float aw = 0.f, ab = 0.f;
#pragma unroll
    for (int e = 0; e < EDIM; ++e) {
        float ev = emb[c * EDIM + e];
        int row = MDIM + l * EDIM + e;
        aw += ev * Wew[row * HDIM + h];
        ab += ev * bew[row * HDIM + h];
    }
    g_TW[(c * LWIN + l) * HDIM + h] = aw;
    g_Tb[(c * LWIN + l) * HDIM + h] = ab;
}

// ---------------- kernel 2: window pre-activations ----------------
__global__ void pre_kernel(const int* __restrict__ x0) {
    int tb = blockIdx.x;
    int t = tb >> 4, b = tb & 15;
    int h = threadIdx.x;
    float aw = 0.f, ab = 0.f;
#pragma unroll 4
    for (int l = 0; l < LWIN; ++l) {
        int k = t + l;
        int tok = (k < LWIN) ? 0 : x0[b * NSTEP + (k - LWIN)];
        aw += g_TW[(tok * LWIN + l) * HDIM + h];
        ab += g_Tb[(tok * LWIN + l) * HDIM + h];
    }
    g_preW[(t * BATCH + b) * HDIM + h] = aw;
    g_preb[(t * BATCH + b) * HDIM + h] = ab;
}

// ---------------- kernel 3: sequential scan ----------------
// 16 clusters (batch) x 8 CTAs (i-slices of 8), 512 threads/CTA.
// Associativity swap: G[h,i] = sum_j Wdec[h,i,j] m[j] runs IN PARALLEL with
// the enc MLP (both depend only on m). res[i] = sum_h hW[h] G[h,i]
//                                            + sum_h hb[h] bdw[h,i]
//                                            + sum_j Wdb[i,j] m[j] + bdb[i].
// Sync: split cluster barrier; SINGLE convergent arrive at loop bottom
// (the R12 bug was arrive.aligned inside divergent branches -> deadlock).
__global__ void __launch_bounds__(512, 1)
scan_kernel(const float* __restrict__ Wew, const float* __restrict__ Web,
            const float* __restrict__ Wdw, const float* __restrict__ Wdb,
            const float* __restrict__ bew, const float* __restrict__ beb,
            const float* __restrict__ bdw, const float* __restrict__ bdb) {
    __shared__ __align__(16) float sM[2][MDIM];   // ping-pong m
    __shared__ __align__(16) float sH[2][HDIM];   // hW, hb
    __shared__ __align__(16) float sG[8 * 64];    // G[il][h]
    __shared__ __align__(16) float sBdw[8 * 64];  // bdw[h, ig] -> [il][h]
    __shared__ __align__(16) float sWdb[8 * 64];  // Wdb[ig*64+j] -> [il][j]
    __shared__ float sP[4 * 128];                 // enc partials

    const int tid = threadIdx.x;
    const int b = blockIdx.x >> 3;
    const int r = blockIdx.x & 7;

    // ---- G identity: gil = tid>>6 (0..7), gh = tid&63
    const int gil = tid >> 6, gh = tid & 63;
    const int ig_g = r * 8 + gil;
    unsigned long long wgp[32];
    {
        const float* wsrc = Wdw + gh * 4096 + ig_g * 64;
#pragma unroll
        for (int k = 0; k < 32; ++k)
            wgp[k] = packf2(wsrc[2 * k], wsrc[2 * k + 1]);
    }

    // ---- enc identity: q = tid>>7, path, h6 (4-way split over j)
    const int q = tid >> 7;
    const int rest = tid & 127;
    const int path = rest >> 6;
    const int h6 = rest & 63;
    const float* Aarr = path ? bew : Wew;
    unsigned long long aencp[8];
#pragma unroll
    for (int k = 0; k < 8; ++k)
        aencp[k] = packf2(Aarr[(q * 16 + 2 * k) * 64 + h6],
                          Aarr[(q * 16 + 2 * k + 1) * 64 + h6]);

    float encb = 0.f;
    const float* pp = nullptr;
    float pre_next = 0.f;
    if (tid < 128) {
        encb = path ? beb[h6] : Web[h6];
        pp = (path ? g_preb : g_preW) + b * 64 + h6;
        pre_next = pp[0];
    }

    float bdbv = 0.f;
    if (tid < 64 && (tid & 7) == 0) bdbv = bdb[r * 8 + (tid >> 3)];

    // small weight tables in smem
    {
        int il = tid >> 6, hh = tid & 63;
        sBdw[il * 64 + hh] = bdw[hh * 64 + r * 8 + il];
        sWdb[il * 64 + hh] = Wdb[(r * 8 + il) * 64 + hh];
    }
    if (tid < 64) sM[0][tid] = 0.f;

    const uint32_t sM_sa = (uint32_t)__cvta_generic_to_shared(&sM[0][0]);

    __syncthreads();
    asm volatile("barrier.cluster.arrive.aligned;\n" ::: "memory");
    asm volatile("barrier.cluster.wait.aligned;\n" ::: "memory");
    // open split-barrier pipeline (matches the wait at top of t=0)
    asm volatile("barrier.cluster.arrive.aligned;\n" ::: "memory");

#pragma unroll 1
    for (int t = 0; t < NSTEP; ++t) {
        // all peers' m[t] stores are visible after this
        asm volatile("barrier.cluster.wait.aligned;\n" ::: "memory");

        const uint32_t mcur_sa = sM_sa + (t & 1) * (MDIM * 4);
        float pre_cur = pre_next;

        // ---- stage A: G (all 512 threads) and enc partials (all 512), parallel
        {
            unsigned long long g0 = 0ull, g1 = 0ull;
#pragma unroll
            for (int k = 0; k < 16; ++k) {
                unsigned long long m0, m1;
                asm volatile("ld.shared.v2.u64 {%0, %1}, [%2];"
                             : "=l"(m0), "=l"(m1) : "r"(mcur_sa + k * 16));
                g0 = fma2(m0, wgp[2 * k], g0);
                g1 = fma2(m1, wgp[2 * k + 1], g1);
            }
            sG[gil * 64 + gh] = hsum2(add2(g0, g1));

            unsigned long long e0 = 0ull, e1 = 0ull;
            uint32_t ma = mcur_sa + q * 64;
#pragma unroll
            for (int k = 0; k < 4; ++k) {
                unsigned long long m0, m1;
                asm volatile("ld.shared.v2.u64 {%0, %1}, [%2];"
                             : "=l"(m0), "=l"(m1) : "r"(ma + k * 16));
                e0 = fma2(m0, aencp[2 * k], e0);
                e1 = fma2(m1, aencp[2 * k + 1], e1);
            }
            sP[q * 128 + rest] = hsum2(add2(e0, e1));
        }
        __syncthreads();

        // ---- stage B: finalize enc z, sigmoid -> sH; prefetch next pre
        if (tid < 128) {
            float z = sP[rest] + sP[128 + rest] + sP[256 + rest] + sP[384 + rest]
                    + pre_cur + encb;
            sH[path][h6] = sigmoidf_fast(z);
            if (t + 1 < NSTEP) pre_next = pp[(t + 1) * (BATCH * 64)];
        }
        __syncthreads();

        // ---- stage C (tid<64): res[i] via h-contraction + bias paths
        if (tid < 64) {
            const int il = tid >> 3, s8 = tid & 7;
            const int base = il * 64 + s8 * 8;
            const float* mcur = sM[t & 1];
            float acc = 0.f;
#pragma unroll
            for (int k = 0; k < 8; ++k) {
                int hh = s8 * 8 + k;
                acc += sH[0][hh] * sG[base + k];
                acc += sH[1][hh] * sBdw[base + k];
                acc += mcur[hh] * sWdb[base + k];
            }
            acc += __shfl_xor_sync(0xffffffffu, acc, 1);
            acc += __shfl_xor_sync(0xffffffffu, acc, 2);
            acc += __shfl_xor_sync(0xffffffffu, acc, 4);
            if (s8 == 0) {
                float nm = sigmoidf_fast(acc + bdbv);
                int nxt = (t + 1) & 1;
                int igo = r * 8 + il;
                sM[nxt][igo] = nm;
                if (t + 1 < NSTEP) {
                    uint32_t a = sM_sa + nxt * (MDIM * 4) + igo * 4;
#pragma unroll
                    for (int p2 = 0; p2 < 8; ++p2) {
                        if (p2 == r) continue;
                        uint32_t ra;
                        asm volatile("mapa.shared::cluster.u32 %0, %1, %2;"
                                     : "=r"(ra) : "r"(a), "r"(p2));
                        asm volatile("st.shared::cluster.f32 [%0], %1;"
                                     :: "r"(ra), "f"(nm) : "memory");
                    }
                }
                g_m[(t * BATCH + b) * MDIM + igo] = nm;
            }
        }
        // SINGLE convergent arrive: release for the DSMEM stores above
        // (store -> arrive in program order on the storing threads)
        asm volatile("barrier.cluster.arrive.aligned;\n" ::: "memory");
    }

    asm volatile("barrier.cluster.wait.aligned;\n" ::: "memory");
}

// ---------------- kernel 4: loss epilogue ----------------
__global__ void __launch_bounds__(256)
loss_kernel(const int* __restrict__ x0, const float* __restrict__ decw,
            const float* __restrict__ decb, float* __restrict__ out) {
    __shared__ float sm[64];
    __shared__ float sred[8];
    __shared__ float syl;
    int row = blockIdx.x;
    int t = row >> 4, b = row & 15;
    int c = threadIdx.x;
    if (c < 64) sm[c] = g_m[row * 64 + c];
    __syncthreads();

    float logit = decb[c];
#pragma unroll
    for (int i = 0; i < 64; ++i)
        logit += sm[i] * decw[i * COUT + c];

    int y = x0[b * NSTEP + t];
    if (c == y) syl = logit;

    float mx = logit;
#pragma unroll
    for (int off = 16; off; off >>= 1)
        mx = fmaxf(mx, __shfl_xor_sync(0xffffffffu, mx, off));
    if ((c & 31) == 0) sred[c >> 5] = mx;
    __syncthreads();
    mx = sred[0];
#pragma unroll
    for (int w = 1; w < 8; ++w) mx = fmaxf(mx, sred[w]);

    float ex = __expf(logit - mx);
#pragma unroll
    for (int off = 16; off; off >>= 1)
        ex += __shfl_xor_sync(0xffffffffu, ex, off);
    __syncthreads();
    if ((c & 31) == 0) sred[c >> 5] = ex;
    __syncthreads();
    if (c == 0) {
        float S = 0.f;
#pragma unroll
        for (int w = 0; w < 8; ++w) S += sred[w];
        float lse = mx + __logf(S);
        out[row] = (lse - syl) * 1.4426950408889634f;
    }
}

// ---------------- launch ----------------
extern "C" void kernel_launch(void* const* d_in, const int* in_sizes, int n_in,
                              void* d_out, int out_size) {
    const int*   x0   = (const int*)d_in[0];
    const float* emb  = (const float*)d_in[1];
    const float* Wew  = (const float*)d_in[2];
    const float* Web  = (const float*)d_in[3];
    const float* Wdw  = (const float*)d_in[4];
    const float* Wdb  = (const float*)d_in[5];
    const float* bew  = (const float*)d_in[6];
    const float* beb  = (const float*)d_in[7];
    const float* bdw  = (const float*)d_in[8];
    const float* bdb  = (const float*)d_in[9];
    const float* decw = (const float*)d_in[10];
    const float* decb = (const float*)d_in[11];
    float* out = (float*)d_out;

    table_kernel<<<CIN * LWIN, 64>>>(emb, Wew, bew);
    pre_kernel<<<NSTEP * BATCH, 64>>>(x0);

    cudaLaunchConfig_t cfg = {};
    cfg.gridDim = dim3(128, 1, 1);
    cfg.blockDim = dim3(512, 1, 1);
    cfg.dynamicSmemBytes = 0;
    cfg.stream = 0;
    cudaLaunchAttribute attr[1];
    attr[0].id = cudaLaunchAttributeClusterDimension;
    attr[0].val.clusterDim.x = 8;
    attr[0].val.clusterDim.y = 1;
    attr[0].val.clusterDim.z = 1;
    cfg.attrs = attr;
    cfg.numAttrs = 1;
    cudaLaunchKernelEx(&cfg, scan_kernel, Wew, Web, Wdw, Wdb, bew, beb, bdw, bdb);

    loss_kernel<<<NSTEP * BATCH, 256>>>(x0, decw, decb, out);
}